// round 10
// baseline (speedup 1.0000x reference)
#include <cuda_runtime.h>
#include <stdint.h>

// BNB 8-bit embedding dequant gather (harness materializes int8 q_weight as int32):
//   out[token,:] = (float)q_weight[x[token],:] * (absmax[x[token]] / 127)
// x[32768] i32, q_weight[50257,1024] i32, absmax[50257] f32, out[32768,1024] f32.
//
// L2-policy version: table gathers use ld.global.nc.L2::evict_last.v4.b64
// (32B — the only width ptxas accepts for evict_last) to pin the 205MB table
// in the 126MB L2; output stores are __stcs (evict-first, never re-read).
// 256 threads = 2 half-groups of 128 lanes x 32B; 8 tokens/CTA as 4 pairs.

static constexpr int DIM = 1024;
static constexpr int THREADS = 256;
static constexpr int TOKENS_PER_CTA = 8;   // 4 pairs
static constexpr int PAIRS = 4;

__device__ __forceinline__ longlong4 ldg_evict_last_32B(const void* p) {
    longlong4 v;
    asm volatile("ld.global.nc.L2::evict_last.v4.b64 {%0,%1,%2,%3}, [%4];"
                 : "=l"(v.x), "=l"(v.y), "=l"(v.z), "=l"(v.w)
                 : "l"(p));
    return v;
}

__global__ __launch_bounds__(THREADS, 6)
void bnb8_embed_kernel(const int* __restrict__ x,
                       const int* __restrict__ qw,
                       const float* __restrict__ absmax,
                       float* __restrict__ out,
                       int n_tokens)
{
    const int base = blockIdx.x * TOKENS_PER_CTA;
    const int half = threadIdx.x >> 7;     // 0 or 1: which token of each pair
    const int lane = threadIdx.x & 127;    // 32B lane within the row

    // Broadcast index loads.
    int rows[PAIRS];
    float scales[PAIRS];
#pragma unroll
    for (int p = 0; p < PAIRS; p++)
        rows[p] = __ldg(x + base + 2 * p + half);

    // 4 independent 32B gathers in flight, L2 evict_last pins the table.
    longlong4 v[PAIRS];
#pragma unroll
    for (int p = 0; p < PAIRS; p++) {
        const char* rp = reinterpret_cast<const char*>(qw)
                       + ((long long)rows[p] * DIM + lane * 8) * 4;
        v[p] = ldg_evict_last_32B(rp);
    }

#pragma unroll
    for (int p = 0; p < PAIRS; p++)
        scales[p] = __ldg(absmax + rows[p]) * (1.0f / 127.0f);

#pragma unroll
    for (int p = 0; p < PAIRS; p++) {
        const float s = scales[p];
        // Unpack 8 int32 from 4x64-bit.
        int q0 = (int)(v[p].x), q1 = (int)(v[p].x >> 32);
        int q2 = (int)(v[p].y), q3 = (int)(v[p].y >> 32);
        int q4 = (int)(v[p].z), q5 = (int)(v[p].z >> 32);
        int q6 = (int)(v[p].w), q7 = (int)(v[p].w >> 32);

        float4 o0 = make_float4((float)q0 * s, (float)q1 * s,
                                (float)q2 * s, (float)q3 * s);
        float4 o1 = make_float4((float)q4 * s, (float)q5 * s,
                                (float)q6 * s, (float)q7 * s);

        float* op = out + (long long)(base + 2 * p + half) * DIM + lane * 8;
        __stcs(reinterpret_cast<float4*>(op),     o0);  // evict-first
        __stcs(reinterpret_cast<float4*>(op) + 1, o1);
    }
}

extern "C" void kernel_launch(void* const* d_in, const int* in_sizes, int n_in,
                              void* d_out, int out_size)
{
    // Bind by element count: qw largest, x smallest, absmax the remaining one.
    long long max_sz = -1;
    int qw_idx = -1;
    for (int i = 0; i < n_in; i++)
        if ((long long)in_sizes[i] > max_sz) { max_sz = in_sizes[i]; qw_idx = i; }

    long long min_sz = 0x7fffffffffffLL;
    int x_idx = -1;
    for (int i = 0; i < n_in; i++) {
        if (i == qw_idx) continue;
        if ((long long)in_sizes[i] < min_sz) { min_sz = in_sizes[i]; x_idx = i; }
    }
    int am_idx = -1;
    for (int i = 0; i < n_in; i++)
        if (i != qw_idx && i != x_idx) am_idx = i;

    const int*   x      = (const int*)d_in[x_idx];
    const int*   qw     = (const int*)d_in[qw_idx];
    const float* absmax = (const float*)d_in[am_idx];
    float*       out    = (float*)d_out;
    const int n_tokens  = in_sizes[x_idx];  // 32768

    const int grid = (n_tokens + TOKENS_PER_CTA - 1) / TOKENS_PER_CTA;
    bnb8_embed_kernel<<<grid, THREADS>>>(x, qw, absmax, out, n_tokens);
}

// round 11
// speedup vs baseline: 1.0491x; 1.0491x over previous
#include <cuda_runtime.h>
#include <stdint.h>

// BNB 8-bit embedding dequant gather (harness materializes int8 q_weight as int32):
//   out[token,:] = (float)q_weight[x[token],:] * (absmax[x[token]] / 127)
// x[32768] i32, q_weight[50257,1024] i32, absmax[50257] f32, out[32768,1024] f32.
//
// Exactly the proven R4 shape (4 tokens/CTA, 256 threads, int4 gathers) with
// ONE change: output stores use __stwt (st.global.wt) instead of __stcs.
// Theory: the 134MB output write stream was allocating in L2 and evicting the
// gather table (~98MB touched working set, fits in 126MB L2). Write-through
// stores keep L2 for the table -> gather reads become L2 hits across replays.

static constexpr int DIM = 1024;
static constexpr int THREADS = 256;        // DIM/4 int4 lanes
static constexpr int TOKENS_PER_CTA = 4;

__global__ __launch_bounds__(THREADS, 8)
void bnb8_embed_kernel(const int* __restrict__ x,
                       const int* __restrict__ qw,
                       const float* __restrict__ absmax,
                       float* __restrict__ out,
                       int n_tokens)
{
    const int base = blockIdx.x * TOKENS_PER_CTA;

    // Broadcast index loads (same addr across CTA -> 1 request + broadcast).
    int rows[TOKENS_PER_CTA];
#pragma unroll
    for (int i = 0; i < TOKENS_PER_CTA; i++)
        rows[i] = __ldg(x + base + i);

    float scales[TOKENS_PER_CTA];
#pragma unroll
    for (int i = 0; i < TOKENS_PER_CTA; i++)
        scales[i] = __ldg(absmax + rows[i]) * (1.0f / 127.0f);

    // 4 independent 16B gathers in flight before any consumption.
    int4 v[TOKENS_PER_CTA];
#pragma unroll
    for (int i = 0; i < TOKENS_PER_CTA; i++) {
        const int4* rp = reinterpret_cast<const int4*>(qw + (long long)rows[i] * DIM);
        v[i] = __ldg(rp + threadIdx.x);
    }

#pragma unroll
    for (int i = 0; i < TOKENS_PER_CTA; i++) {
        float4 o;
        o.x = (float)v[i].x * scales[i];
        o.y = (float)v[i].y * scales[i];
        o.z = (float)v[i].z * scales[i];
        o.w = (float)v[i].w * scales[i];
        float4* op = reinterpret_cast<float4*>(out + (long long)(base + i) * DIM);
        __stwt(op + threadIdx.x, o);   // write-through: don't displace table in L2
    }
}

extern "C" void kernel_launch(void* const* d_in, const int* in_sizes, int n_in,
                              void* d_out, int out_size)
{
    // Bind by element count: qw largest, x smallest, absmax the remaining one.
    long long max_sz = -1;
    int qw_idx = -1;
    for (int i = 0; i < n_in; i++)
        if ((long long)in_sizes[i] > max_sz) { max_sz = in_sizes[i]; qw_idx = i; }

    long long min_sz = 0x7fffffffffffLL;
    int x_idx = -1;
    for (int i = 0; i < n_in; i++) {
        if (i == qw_idx) continue;
        if ((long long)in_sizes[i] < min_sz) { min_sz = in_sizes[i]; x_idx = i; }
    }
    int am_idx = -1;
    for (int i = 0; i < n_in; i++)
        if (i != qw_idx && i != x_idx) am_idx = i;

    const int*   x      = (const int*)d_in[x_idx];
    const int*   qw     = (const int*)d_in[qw_idx];
    const float* absmax = (const float*)d_in[am_idx];
    float*       out    = (float*)d_out;
    const int n_tokens  = in_sizes[x_idx];  // 32768

    const int grid = (n_tokens + TOKENS_PER_CTA - 1) / TOKENS_PER_CTA;
    bnb8_embed_kernel<<<grid, THREADS>>>(x, qw, absmax, out, n_tokens);
}